// round 13
// baseline (speedup 1.0000x reference)
#include <cuda_runtime.h>
#include <cuda_bf16.h>
#include <cstdint>

// Problem constants
#define RR 8
#define BB 16
#define DD 32
#define HH 128
#define NN 2048
#define FF 256
#define HALF_LOG_2PI 0.9189385332046727f

#define NTHREADS 320
#define NWARPS   10
#define BANDROWS 32
#define NBANDS   (NN / BANDROWS)    // 64 bands, warp w takes w, w+10, ...

// SMEM strides (elements)
#define WS1 136   // W1: [32][136] bf16   (272B row stride -> ldsm conflict-free)
#define WS2 136   // W2: [128][136] bf16
#define WS3 72    // W3: [128][72] bf16   (144B row stride -> conflict-free)
#define XSF 34    // x slab fp32: [32][34] per warp (even stride -> aligned float2)

// SMEM layout (bytes) — h1/h2 live in registers (C-frag == next A-frag)
#define OFF_W1 0
#define SZ_W1  (32*WS1*2)        // 8704
#define OFF_W2 (OFF_W1+SZ_W1)
#define SZ_W2  (128*WS2*2)       // 34816
#define OFF_W3 (OFF_W2+SZ_W2)
#define SZ_W3  (128*WS3*2)       // 18432
#define OFF_XF (OFF_W3+SZ_W3)
#define SZ_XF  (NWARPS*BANDROWS*XSF*4)   // 43520 (warp-private 32-row slabs)
#define OFF_RIDX (OFF_XF+SZ_XF)
#define SMEM_TOTAL (OFF_RIDX + 128)      // ~105600 bytes

// x4 trans: lanes 0-15 address matrices 0,1 (b0,b1 = n-subtile lo),
//           lanes 16-31 address matrices 2,3 (b0,b1 = n-subtile hi)
__device__ __forceinline__ void ldsm_x4_trans(uint32_t b[4], uint32_t addr) {
    asm volatile("ldmatrix.sync.aligned.m8n8.x4.trans.shared.b16 {%0,%1,%2,%3}, [%4];"
                 : "=r"(b[0]), "=r"(b[1]), "=r"(b[2]), "=r"(b[3]) : "r"(addr));
}

__device__ __forceinline__ void mma16816(float c[4], const uint32_t a[4],
                                         uint32_t b0, uint32_t b1) {
    asm volatile("mma.sync.aligned.m16n8k16.row.col.f32.bf16.bf16.f32 "
                 "{%0,%1,%2,%3}, {%4,%5,%6,%7}, {%8,%9}, {%0,%1,%2,%3};"
                 : "+f"(c[0]), "+f"(c[1]), "+f"(c[2]), "+f"(c[3])
                 : "r"(a[0]), "r"(a[1]), "r"(a[2]), "r"(a[3]), "r"(b0), "r"(b1));
}

__device__ __forceinline__ uint32_t pack_relu(float a, float b) {
    __nv_bfloat162 v = __float22bfloat162_rn(make_float2(fmaxf(a, 0.f), fmaxf(b, 0.f)));
    return *reinterpret_cast<uint32_t*>(&v);
}

__device__ __forceinline__ uint32_t pack_bf2(float a, float b) {
    __nv_bfloat162 v = __float22bfloat162_rn(make_float2(a, b));
    return *reinterpret_cast<uint32_t*>(&v);
}

__global__ __launch_bounds__(NTHREADS, 1)
void flow_kernel(const float* __restrict__ x,  const float* __restrict__ W1,
                 const float* __restrict__ W2, const float* __restrict__ W3,
                 const float* __restrict__ M1, const float* __restrict__ M2,
                 const float* __restrict__ M3, const int* __restrict__ region_idx,
                 float* __restrict__ out)
{
    extern __shared__ unsigned char smem[];
    __nv_bfloat16* w1s = (__nv_bfloat16*)(smem + OFF_W1);
    __nv_bfloat16* w2s = (__nv_bfloat16*)(smem + OFF_W2);
    __nv_bfloat16* w3s = (__nv_bfloat16*)(smem + OFF_W3);
    float*         xsf = (float*)        (smem + OFF_XF);
    int*          ridx = (int*)          (smem + OFF_RIDX);

    const int bx   = blockIdx.x;        // network id: r*B + b
    const int r    = bx >> 4;           // B = 16
    const int tid  = threadIdx.x;
    const int w    = tid >> 5;          // warp 0..9
    const int lane = tid & 31;

    if (tid < DD) ridx[tid] = region_idx[r * DD + tid];

    // ---- Pre-mask weights into bf16 SMEM (one-time per CTA) ----
    {
        const float* W1p = W1 + (size_t)bx * DD * HH;
        const float* M1p = M1 + (size_t)bx * DD * HH;
        for (int i = tid; i < DD * HH; i += NTHREADS) {
            int d = i >> 7, h = i & 127;
            w1s[d * WS1 + h] = __float2bfloat16(W1p[i] * M1p[i]);
        }
        const float* W2p = W2 + (size_t)bx * HH * HH;
        const float* M2p = M2 + (size_t)bx * HH * HH;
        for (int i = tid; i < HH * HH; i += NTHREADS) {
            int k = i >> 7, j = i & 127;
            w2s[k * WS2 + j] = __float2bfloat16(W2p[i] * M2p[i]);
        }
        const float* W3p = W3 + (size_t)bx * HH * 2 * DD;
        const float* M3p = M3 + (size_t)bx * HH * 2 * DD;
        for (int i = tid; i < HH * 2 * DD; i += NTHREADS) {
            int k = i >> 6, o = i & 63;
            w3s[k * WS3 + o] = __float2bfloat16(W3p[i] * M3p[i]);
        }
    }
    __syncthreads();

    const int g    = lane >> 2;
    const int q    = lane & 3;
    const int l16  = lane & 15;
    const int lhi  = lane >> 4;
    const int col  = ridx[lane];        // lane <-> feature column (D == 32 lanes)

    const uint32_t sbase = (uint32_t)__cvta_generic_to_shared(smem);
    const uint32_t b_w1_addr = sbase + OFF_W1 + (l16 * WS1 + lhi * 8) * 2;
    const uint32_t b_w2_addr = sbase + OFF_W2 + (l16 * WS2 + lhi * 8) * 2;
    const uint32_t b_w3_addr = sbase + OFF_W3 + (l16 * WS3 + lhi * 8) * 2;

    // warp-private 32-row x slab + per-m-tile row pointers
    float* xs = xsf + w * (BANDROWS * XSF);
    const float* xr0[2] = { xs + g * XSF,        xs + (16 + g) * XSF };
    const float* xr1[2] = { xs + (g + 8) * XSF,  xs + (24 + g) * XSF };

    // warp w processes bands w, w+10, w+20, ... (each 32 rows); fully warp-private
    for (int band = w; band < NBANDS; band += NWARPS) {
        const int t0 = band * BANDROWS;

        // ---- Load x band (32 rows, lane = feature col) ----
        #pragma unroll 4
        for (int rr = 0; rr < BANDROWS; ++rr)
            xs[rr * XSF + lane] = x[(size_t)(t0 + rr) * FF + col];
        __syncwarp();

        // ---- Build GEMM1 A-fragments straight from fp32 x ----
        uint32_t a1[2][2][4];    // [m-tile][k-block]
        #pragma unroll
        for (int m = 0; m < 2; ++m)
            #pragma unroll
            for (int k = 0; k < 2; ++k) {
                float2 p0 = *(const float2*)(xr0[m] + 16 * k + 2 * q);
                float2 p1 = *(const float2*)(xr1[m] + 16 * k + 2 * q);
                float2 p2 = *(const float2*)(xr0[m] + 16 * k + 2 * q + 8);
                float2 p3 = *(const float2*)(xr1[m] + 16 * k + 2 * q + 8);
                a1[m][k][0] = pack_bf2(p0.x, p0.y);
                a1[m][k][1] = pack_bf2(p1.x, p1.y);
                a1[m][k][2] = pack_bf2(p2.x, p2.y);
                a1[m][k][3] = pack_bf2(p3.x, p3.y);
            }

        // ---- GEMM1: h1 = relu(x[32,32] @ W1[32,128]) -> registers (a2 frags) ----
        uint32_t a2[2][8][4];
        #pragma unroll
        for (int p = 0; p < 4; ++p) {       // n-tile pair (2p, 2p+1)
            float cA[2][2][4], cB[2][2][4];
            #pragma unroll
            for (int m = 0; m < 2; ++m)
                #pragma unroll
                for (int s = 0; s < 2; ++s)
                    #pragma unroll
                    for (int e = 0; e < 4; ++e) { cA[m][s][e] = 0.f; cB[m][s][e] = 0.f; }
            #pragma unroll
            for (int k = 0; k < 2; ++k) {
                uint32_t bA[4], bB[4];
                ldsm_x4_trans(bA, b_w1_addr + (k * 16 * WS1 + (2*p)   * 16) * 2);
                ldsm_x4_trans(bB, b_w1_addr + (k * 16 * WS1 + (2*p+1) * 16) * 2);
                #pragma unroll
                for (int m = 0; m < 2; ++m) {
                    mma16816(cA[m][0], a1[m][k], bA[0], bA[1]);
                    mma16816(cA[m][1], a1[m][k], bA[2], bA[3]);
                    mma16816(cB[m][0], a1[m][k], bB[0], bB[1]);
                    mma16816(cB[m][1], a1[m][k], bB[2], bB[3]);
                }
            }
            #pragma unroll
            for (int m = 0; m < 2; ++m) {
                a2[m][2*p][0]   = pack_relu(cA[m][0][0], cA[m][0][1]);
                a2[m][2*p][1]   = pack_relu(cA[m][0][2], cA[m][0][3]);
                a2[m][2*p][2]   = pack_relu(cA[m][1][0], cA[m][1][1]);
                a2[m][2*p][3]   = pack_relu(cA[m][1][2], cA[m][1][3]);
                a2[m][2*p+1][0] = pack_relu(cB[m][0][0], cB[m][0][1]);
                a2[m][2*p+1][1] = pack_relu(cB[m][0][2], cB[m][0][3]);
                a2[m][2*p+1][2] = pack_relu(cB[m][1][0], cB[m][1][1]);
                a2[m][2*p+1][3] = pack_relu(cB[m][1][2], cB[m][1][3]);
            }
        }

        // ---- GEMM2: h2 = relu(h1 @ W2) -> registers (a3 frags) ----
        uint32_t a3[2][8][4];
        #pragma unroll
        for (int p = 0; p < 4; ++p) {
            float cA[2][2][4], cB[2][2][4];
            #pragma unroll
            for (int m = 0; m < 2; ++m)
                #pragma unroll
                for (int s = 0; s < 2; ++s)
                    #pragma unroll
                    for (int e = 0; e < 4; ++e) { cA[m][s][e] = 0.f; cB[m][s][e] = 0.f; }
            #pragma unroll
            for (int k = 0; k < 8; ++k) {
                uint32_t bA[4], bB[4];
                ldsm_x4_trans(bA, b_w2_addr + (k * 16 * WS2 + (2*p)   * 16) * 2);
                ldsm_x4_trans(bB, b_w2_addr + (k * 16 * WS2 + (2*p+1) * 16) * 2);
                #pragma unroll
                for (int m = 0; m < 2; ++m) {
                    mma16816(cA[m][0], a2[m][k], bA[0], bA[1]);
                    mma16816(cA[m][1], a2[m][k], bA[2], bA[3]);
                    mma16816(cB[m][0], a2[m][k], bB[0], bB[1]);
                    mma16816(cB[m][1], a2[m][k], bB[2], bB[3]);
                }
            }
            #pragma unroll
            for (int m = 0; m < 2; ++m) {
                a3[m][2*p][0]   = pack_relu(cA[m][0][0], cA[m][0][1]);
                a3[m][2*p][1]   = pack_relu(cA[m][0][2], cA[m][0][3]);
                a3[m][2*p][2]   = pack_relu(cA[m][1][0], cA[m][1][1]);
                a3[m][2*p][3]   = pack_relu(cA[m][1][2], cA[m][1][3]);
                a3[m][2*p+1][0] = pack_relu(cB[m][0][0], cB[m][0][1]);
                a3[m][2*p+1][1] = pack_relu(cB[m][0][2], cB[m][0][3]);
                a3[m][2*p+1][2] = pack_relu(cB[m][1][0], cB[m][1][1]);
                a3[m][2*p+1][3] = pack_relu(cB[m][1][2], cB[m][1][3]);
            }
        }

        // ---- GEMM3 + MAF epilogue (h2 already in registers as A-frags) ----
        float acc0[2] = {0.f, 0.f}, acc1[2] = {0.f, 0.f};
        #pragma unroll
        for (int p = 0; p < 2; ++p) {       // 4 n-tile-pairs total -> 2 pair-groups
            float cA[2][2][4], cB[2][2][4];
            #pragma unroll
            for (int m = 0; m < 2; ++m)
                #pragma unroll
                for (int s = 0; s < 2; ++s)
                    #pragma unroll
                    for (int e = 0; e < 4; ++e) { cA[m][s][e] = 0.f; cB[m][s][e] = 0.f; }
            #pragma unroll
            for (int k = 0; k < 8; ++k) {
                uint32_t bA[4], bB[4];
                ldsm_x4_trans(bA, b_w3_addr + (k * 16 * WS3 + (2*p)   * 16) * 2);
                ldsm_x4_trans(bB, b_w3_addr + (k * 16 * WS3 + (2*p+1) * 16) * 2);
                #pragma unroll
                for (int m = 0; m < 2; ++m) {
                    mma16816(cA[m][0], a3[m][k], bA[0], bA[1]);
                    mma16816(cA[m][1], a3[m][k], bA[2], bA[3]);
                    mma16816(cB[m][0], a3[m][k], bB[0], bB[1]);
                    mma16816(cB[m][1], a3[m][k], bB[2], bB[3]);
                }
            }
            // cols (2d, 2d+1) = (shift, log_scale) in the same thread:
            // nt2: even sub-tile d = 8*nt2 + q, odd sub-tile d = 8*nt2 + 4 + q
            #pragma unroll
            for (int m = 0; m < 2; ++m)
                #pragma unroll
                for (int s = 0; s < 2; ++s) {   // s=0 -> nt2=2p (cA), s=1 -> nt2=2p+1 (cB)
                    const float (*cc)[4] = s ? cB[m] : cA[m];
                    int de = 8 * (2*p + s) + q, dd = de + 4;
                    float u0 = (xr0[m][de] - cc[0][0]) * __expf(-cc[0][1]);
                    float u1 = (xr1[m][de] - cc[0][2]) * __expf(-cc[0][3]);
                    float u2 = (xr0[m][dd] - cc[1][0]) * __expf(-cc[1][1]);
                    float u3 = (xr1[m][dd] - cc[1][2]) * __expf(-cc[1][3]);
                    acc0[m] += -0.5f * u0 * u0 - HALF_LOG_2PI - cc[0][1];
                    acc1[m] += -0.5f * u1 * u1 - HALF_LOG_2PI - cc[0][3];
                    acc0[m] += -0.5f * u2 * u2 - HALF_LOG_2PI - cc[1][1];
                    acc1[m] += -0.5f * u3 * u3 - HALF_LOG_2PI - cc[1][3];
                }
        }
        // quad reduction over the 4 lanes sharing a row (covers all 32 d)
        #pragma unroll
        for (int m = 0; m < 2; ++m) {
            acc0[m] += __shfl_xor_sync(0xffffffffu, acc0[m], 1);
            acc0[m] += __shfl_xor_sync(0xffffffffu, acc0[m], 2);
            acc1[m] += __shfl_xor_sync(0xffffffffu, acc1[m], 1);
            acc1[m] += __shfl_xor_sync(0xffffffffu, acc1[m], 2);
        }
        if (q == 0) {
            out[(size_t)(t0 + g)      * (RR * BB) + bx] = acc0[0];
            out[(size_t)(t0 + g + 8)  * (RR * BB) + bx] = acc1[0];
            out[(size_t)(t0 + 16 + g) * (RR * BB) + bx] = acc0[1];
            out[(size_t)(t0 + 24 + g) * (RR * BB) + bx] = acc1[1];
        }
        __syncwarp();   // protect private x slab before next band overwrites
    }
}

extern "C" void kernel_launch(void* const* d_in, const int* in_sizes, int n_in,
                              void* d_out, int out_size)
{
    const float* x   = (const float*)d_in[0];
    const float* W1  = (const float*)d_in[1];
    const float* W2  = (const float*)d_in[2];
    const float* W3  = (const float*)d_in[3];
    const float* M1  = (const float*)d_in[4];
    const float* M2  = (const float*)d_in[5];
    const float* M3  = (const float*)d_in[6];
    const int*  ridx = (const int*)  d_in[7];
    float* out = (float*)d_out;

    cudaFuncSetAttribute(flow_kernel, cudaFuncAttributeMaxDynamicSharedMemorySize,
                         SMEM_TOTAL);
    flow_kernel<<<RR * BB, NTHREADS, SMEM_TOTAL>>>(x, W1, W2, W3, M1, M2, M3, ridx, out);
}

// round 14
// speedup vs baseline: 1.2758x; 1.2758x over previous
#include <cuda_runtime.h>
#include <cuda_bf16.h>
#include <cstdint>

// Problem constants
#define RR 8
#define BB 16
#define DD 32
#define HH 128
#define NN 2048
#define FF 256
#define HALF_LOG_2PI 0.9189385332046727f

#define TILE 256          // rows per tile (16 warps x 16-row bands)
#define TILES_PER_NET (NN / TILE)          // 8
#define TOTAL_UNITS (RR * BB * TILES_PER_NET)   // 1024
#define NCTAS 148

// SMEM strides (elements)
#define WS1 136   // W1: [32][136] bf16   (272B row stride -> ldsm conflict-free)
#define WS2 136   // W2: [128][136] bf16
#define WS3 72    // W3: [128][72] bf16   (144B row stride -> conflict-free)
#define XSF 34    // x tile fp32: [256][34] (even stride -> aligned float2 loads)

// SMEM layout (bytes) — h1/h2 live in registers (C-frag == next A-frag)
#define OFF_W1 0
#define SZ_W1  (32*WS1*2)        // 8704
#define OFF_W2 (OFF_W1+SZ_W1)
#define SZ_W2  (128*WS2*2)       // 34816
#define OFF_W3 (OFF_W2+SZ_W2)
#define SZ_W3  (128*WS3*2)       // 18432
#define OFF_XF (OFF_W3+SZ_W3)
#define SZ_XF  (TILE*XSF*4)      // 34816
#define OFF_RIDX (OFF_XF+SZ_XF)
#define SMEM_TOTAL (OFF_RIDX + 128)   // 96896 bytes

// x4 trans: lanes 0-15 address matrices 0,1 (b0,b1 for n-tile 2*p),
//           lanes 16-31 address matrices 2,3 (b0,b1 for n-tile 2*p+1)
__device__ __forceinline__ void ldsm_x4_trans(uint32_t b[4], uint32_t addr) {
    asm volatile("ldmatrix.sync.aligned.m8n8.x4.trans.shared.b16 {%0,%1,%2,%3}, [%4];"
                 : "=r"(b[0]), "=r"(b[1]), "=r"(b[2]), "=r"(b[3]) : "r"(addr));
}

__device__ __forceinline__ void mma16816(float c[4], const uint32_t a[4],
                                         uint32_t b0, uint32_t b1) {
    asm volatile("mma.sync.aligned.m16n8k16.row.col.f32.bf16.bf16.f32 "
                 "{%0,%1,%2,%3}, {%4,%5,%6,%7}, {%8,%9}, {%0,%1,%2,%3};"
                 : "+f"(c[0]), "+f"(c[1]), "+f"(c[2]), "+f"(c[3])
                 : "r"(a[0]), "r"(a[1]), "r"(a[2]), "r"(a[3]), "r"(b0), "r"(b1));
}

__device__ __forceinline__ uint32_t pack_relu(float a, float b) {
    __nv_bfloat162 v = __float22bfloat162_rn(make_float2(fmaxf(a, 0.f), fmaxf(b, 0.f)));
    return *reinterpret_cast<uint32_t*>(&v);
}

__device__ __forceinline__ uint32_t pack_bf2(float a, float b) {
    __nv_bfloat162 v = __float22bfloat162_rn(make_float2(a, b));
    return *reinterpret_cast<uint32_t*>(&v);
}

__global__ __launch_bounds__(512, 1)
void flow_kernel(const float* __restrict__ x,  const float* __restrict__ W1,
                 const float* __restrict__ W2, const float* __restrict__ W3,
                 const float* __restrict__ M1, const float* __restrict__ M2,
                 const float* __restrict__ M3, const int* __restrict__ region_idx,
                 float* __restrict__ out)
{
    extern __shared__ unsigned char smem[];
    __nv_bfloat16* w1s = (__nv_bfloat16*)(smem + OFF_W1);
    __nv_bfloat16* w2s = (__nv_bfloat16*)(smem + OFF_W2);
    __nv_bfloat16* w3s = (__nv_bfloat16*)(smem + OFF_W3);
    float*         xsf = (float*)        (smem + OFF_XF);
    int*          ridx = (int*)          (smem + OFF_RIDX);

    const int tid  = threadIdx.x;
    const int w    = tid >> 5;          // warp 0..15
    const int lane = tid & 31;

    const int g    = lane >> 2;
    const int q    = lane & 3;
    const int l16  = lane & 15;
    const int lhi  = lane >> 4;
    const int mrow = w * 16;            // warp-private 16-row band within tile

    const uint32_t sbase = (uint32_t)__cvta_generic_to_shared(smem);
    const uint32_t b_w1_addr = sbase + OFF_W1 + (l16 * WS1 + lhi * 8) * 2;
    const uint32_t b_w2_addr = sbase + OFF_W2 + (l16 * WS2 + lhi * 8) * 2;
    const uint32_t b_w3_addr = sbase + OFF_W3 + (l16 * WS3 + lhi * 8) * 2;

    const float* xr0 = xsf + (mrow + g)     * XSF;   // epilogue / A-frag row ptrs
    const float* xr1 = xsf + (mrow + g + 8) * XSF;

    // ---- Persistent balanced schedule over 1024 (network, tile) units ----
    int       u  = (TOTAL_UNITS * blockIdx.x)       / NCTAS;
    const int u1 = (TOTAL_UNITS * (blockIdx.x + 1)) / NCTAS;

    while (u < u1) {
        const int net = u >> 3;         // network id r*B + b
        const int r   = net >> 4;       // B = 16

        // ---- Pre-mask this network's weights into bf16 SMEM ----
        __syncthreads();                // all warps done with previous weights
        if (tid < DD) ridx[tid] = region_idx[r * DD + tid];
        {
            const float* W1p = W1 + (size_t)net * DD * HH;
            const float* M1p = M1 + (size_t)net * DD * HH;
            for (int i = tid; i < DD * HH; i += 512) {
                int d = i >> 7, h = i & 127;
                w1s[d * WS1 + h] = __float2bfloat16(W1p[i] * M1p[i]);
            }
            const float* W2p = W2 + (size_t)net * HH * HH;
            const float* M2p = M2 + (size_t)net * HH * HH;
            for (int i = tid; i < HH * HH; i += 512) {
                int k = i >> 7, j = i & 127;
                w2s[k * WS2 + j] = __float2bfloat16(W2p[i] * M2p[i]);
            }
            const float* W3p = W3 + (size_t)net * HH * 2 * DD;
            const float* M3p = M3 + (size_t)net * HH * 2 * DD;
            for (int i = tid; i < HH * 2 * DD; i += 512) {
                int k = i >> 6, o = i & 63;
                w3s[k * WS3 + o] = __float2bfloat16(W3p[i] * M3p[i]);
            }
        }
        __syncthreads();
        const int col = ridx[lane];     // lane <-> feature column for this region

        const int uend = min(u1, (net + 1) * TILES_PER_NET);
        for (; u < uend; ++u) {
            const int t0 = (u & 7) * TILE;

            // ---- Load x tile (warp-private rows, lane = feature col) ----
            #pragma unroll 4
            for (int rr = 0; rr < 16; ++rr) {
                int row = mrow + rr;
                xsf[row * XSF + lane] = x[(size_t)(t0 + row) * FF + col];
            }
            __syncwarp();

            // ---- Build GEMM1 A-fragments straight from fp32 x ----
            uint32_t a1[2][4];
            #pragma unroll
            for (int k = 0; k < 2; ++k) {
                float2 p0 = *(const float2*)(xr0 + 16 * k + 2 * q);
                float2 p1 = *(const float2*)(xr1 + 16 * k + 2 * q);
                float2 p2 = *(const float2*)(xr0 + 16 * k + 2 * q + 8);
                float2 p3 = *(const float2*)(xr1 + 16 * k + 2 * q + 8);
                a1[k][0] = pack_bf2(p0.x, p0.y);
                a1[k][1] = pack_bf2(p1.x, p1.y);
                a1[k][2] = pack_bf2(p2.x, p2.y);
                a1[k][3] = pack_bf2(p3.x, p3.y);
            }

            // ---- GEMM1: h1 = relu(x[16,32] @ W1[32,128]) -> registers (a2) ----
            // C-fragment of n-block nt2 IS the A-fragment of k-block nt2 of GEMM2.
            uint32_t a2[8][4];
            #pragma unroll
            for (int p = 0; p < 4; ++p) {       // n-tile pairs for ILP
                float cA[2][4] = {{0.f,0.f,0.f,0.f},{0.f,0.f,0.f,0.f}};
                float cB[2][4] = {{0.f,0.f,0.f,0.f},{0.f,0.f,0.f,0.f}};
                #pragma unroll
                for (int k = 0; k < 2; ++k) {
                    uint32_t bA[4], bB[4];
                    ldsm_x4_trans(bA, b_w1_addr + (k * 16 * WS1 + (2*p)   * 16) * 2);
                    ldsm_x4_trans(bB, b_w1_addr + (k * 16 * WS1 + (2*p+1) * 16) * 2);
                    mma16816(cA[0], a1[k], bA[0], bA[1]);
                    mma16816(cA[1], a1[k], bA[2], bA[3]);
                    mma16816(cB[0], a1[k], bB[0], bB[1]);
                    mma16816(cB[1], a1[k], bB[2], bB[3]);
                }
                a2[2*p][0]   = pack_relu(cA[0][0], cA[0][1]);
                a2[2*p][1]   = pack_relu(cA[0][2], cA[0][3]);
                a2[2*p][2]   = pack_relu(cA[1][0], cA[1][1]);
                a2[2*p][3]   = pack_relu(cA[1][2], cA[1][3]);
                a2[2*p+1][0] = pack_relu(cB[0][0], cB[0][1]);
                a2[2*p+1][1] = pack_relu(cB[0][2], cB[0][3]);
                a2[2*p+1][2] = pack_relu(cB[1][0], cB[1][1]);
                a2[2*p+1][3] = pack_relu(cB[1][2], cB[1][3]);
            }

            // ---- GEMM2: h2 = relu(h1 @ W2) -> registers (a3) ----
            uint32_t a3[8][4];
            #pragma unroll
            for (int p = 0; p < 4; ++p) {
                float cA[2][4] = {{0.f,0.f,0.f,0.f},{0.f,0.f,0.f,0.f}};
                float cB[2][4] = {{0.f,0.f,0.f,0.f},{0.f,0.f,0.f,0.f}};
                #pragma unroll
                for (int k = 0; k < 8; ++k) {
                    uint32_t bA[4], bB[4];
                    ldsm_x4_trans(bA, b_w2_addr + (k * 16 * WS2 + (2*p)   * 16) * 2);
                    ldsm_x4_trans(bB, b_w2_addr + (k * 16 * WS2 + (2*p+1) * 16) * 2);
                    mma16816(cA[0], a2[k], bA[0], bA[1]);
                    mma16816(cA[1], a2[k], bA[2], bA[3]);
                    mma16816(cB[0], a2[k], bB[0], bB[1]);
                    mma16816(cB[1], a2[k], bB[2], bB[3]);
                }
                a3[2*p][0]   = pack_relu(cA[0][0], cA[0][1]);
                a3[2*p][1]   = pack_relu(cA[0][2], cA[0][3]);
                a3[2*p][2]   = pack_relu(cA[1][0], cA[1][1]);
                a3[2*p][3]   = pack_relu(cA[1][2], cA[1][3]);
                a3[2*p+1][0] = pack_relu(cB[0][0], cB[0][1]);
                a3[2*p+1][1] = pack_relu(cB[0][2], cB[0][3]);
                a3[2*p+1][2] = pack_relu(cB[1][0], cB[1][1]);
                a3[2*p+1][3] = pack_relu(cB[1][2], cB[1][3]);
            }

            // ---- GEMM3 + MAF epilogue (h2 already in registers as A-frags) ----
            float acc0 = 0.f, acc1 = 0.f;
            #pragma unroll
            for (int p = 0; p < 2; ++p) {
                float cA[2][4] = {{0.f,0.f,0.f,0.f},{0.f,0.f,0.f,0.f}};
                float cB[2][4] = {{0.f,0.f,0.f,0.f},{0.f,0.f,0.f,0.f}};
                #pragma unroll
                for (int k = 0; k < 8; ++k) {
                    uint32_t bA[4], bB[4];
                    ldsm_x4_trans(bA, b_w3_addr + (k * 16 * WS3 + (2*p)   * 16) * 2);
                    ldsm_x4_trans(bB, b_w3_addr + (k * 16 * WS3 + (2*p+1) * 16) * 2);
                    mma16816(cA[0], a3[k], bA[0], bA[1]);
                    mma16816(cA[1], a3[k], bA[2], bA[3]);
                    mma16816(cB[0], a3[k], bB[0], bB[1]);
                    mma16816(cB[1], a3[k], bB[2], bB[3]);
                }
                // cols (2d, 2d+1) = (shift, log_scale) in the same thread:
                // nt2: even sub-tile d = 8*nt2 + q, odd sub-tile d = 8*nt2 + 4 + q
                #pragma unroll
                for (int s = 0; s < 2; ++s) {
                    const float (*cc)[4] = s ? cB : cA;
                    int de = 8 * (2*p + s) + q, dd = de + 4;
                    float u0 = (xr0[de] - cc[0][0]) * __expf(-cc[0][1]);
                    float u1v = (xr1[de] - cc[0][2]) * __expf(-cc[0][3]);
                    float u2 = (xr0[dd] - cc[1][0]) * __expf(-cc[1][1]);
                    float u3 = (xr1[dd] - cc[1][2]) * __expf(-cc[1][3]);
                    acc0 += -0.5f * u0  * u0  - HALF_LOG_2PI - cc[0][1];
                    acc1 += -0.5f * u1v * u1v - HALF_LOG_2PI - cc[0][3];
                    acc0 += -0.5f * u2  * u2  - HALF_LOG_2PI - cc[1][1];
                    acc1 += -0.5f * u3  * u3  - HALF_LOG_2PI - cc[1][3];
                }
            }
            // quad reduction over the 4 lanes sharing a row (covers all 32 d)
            acc0 += __shfl_xor_sync(0xffffffffu, acc0, 1);
            acc0 += __shfl_xor_sync(0xffffffffu, acc0, 2);
            acc1 += __shfl_xor_sync(0xffffffffu, acc1, 1);
            acc1 += __shfl_xor_sync(0xffffffffu, acc1, 2);
            if (q == 0) {
                out[(size_t)(t0 + mrow + g)     * (RR * BB) + net] = acc0;
                out[(size_t)(t0 + mrow + g + 8) * (RR * BB) + net] = acc1;
            }
            __syncwarp();   // protect x tile before next iteration overwrites
        }
    }
}

extern "C" void kernel_launch(void* const* d_in, const int* in_sizes, int n_in,
                              void* d_out, int out_size)
{
    const float* x   = (const float*)d_in[0];
    const float* W1  = (const float*)d_in[1];
    const float* W2  = (const float*)d_in[2];
    const float* W3  = (const float*)d_in[3];
    const float* M1  = (const float*)d_in[4];
    const float* M2  = (const float*)d_in[5];
    const float* M3  = (const float*)d_in[6];
    const int*  ridx = (const int*)  d_in[7];
    float* out = (float*)d_out;

    cudaFuncSetAttribute(flow_kernel, cudaFuncAttributeMaxDynamicSharedMemorySize,
                         SMEM_TOTAL);
    flow_kernel<<<NCTAS, 512, SMEM_TOTAL>>>(x, W1, W2, W3, M1, M2, M3, ridx, out);
}

// round 15
// speedup vs baseline: 1.3417x; 1.0517x over previous
#include <cuda_runtime.h>
#include <cuda_bf16.h>
#include <cstdint>

// Problem constants
#define RR 8
#define BB 16
#define DD 32
#define HH 128
#define NN 2048
#define FF 256
#define HALF_LOG_2PI 0.9189385332046727f

#define TILE 256          // rows per tile (16 warps x 16-row bands)
#define TILES_PER_NET (NN / TILE)          // 8
#define TOTAL_UNITS (RR * BB * TILES_PER_NET)   // 1024
#define NCTAS 148

// SMEM strides (elements)
#define WS1 136   // W1: [32][136] bf16   (272B row stride -> ldsm conflict-free)
#define WS2 136   // W2: [128][136] bf16
#define WS3 72    // W3: [128][72] bf16   (144B row stride -> conflict-free)
#define XSF 34    // x tile fp32: [256][34] (even stride -> aligned float2 loads)

// SMEM layout (bytes) — h1/h2 live in registers (C-frag == next A-frag)
#define OFF_W1 0
#define SZ_W1  (32*WS1*2)        // 8704
#define OFF_W2 (OFF_W1+SZ_W1)
#define SZ_W2  (128*WS2*2)       // 34816
#define OFF_W3 (OFF_W2+SZ_W2)
#define SZ_W3  (128*WS3*2)       // 18432
#define OFF_XF (OFF_W3+SZ_W3)
#define SZ_XF  (TILE*XSF*4)      // 34816
#define OFF_RIDX (OFF_XF+SZ_XF)
#define SMEM_TOTAL (OFF_RIDX + 128)   // 96896 bytes

// Degree-sort permutation of the hidden dimension.
// h_deg[i] = (i % 31) + 1; stable ascending sort position:
//   pos(i) = 4*(i%31) + min(i%31, 4) + i/31
// After relabeling, M2 (h_deg[k] <= h_deg[j]) is block-upper-triangular with
// zero blocks aligned to 16-row boundaries: n-tile pair p (sorted cols
// 32p..32p+31, max degree {7,15,23,31}) needs only k-blocks 0..2p+1.
__device__ __forceinline__ int hpos(int i) {
    int d = i % 31;
    return 4 * d + (d < 4 ? d : 4) + i / 31;
}

// x4 trans: lanes 0-15 address matrices 0,1 (b0,b1 for n-tile 2*p),
//           lanes 16-31 address matrices 2,3 (b0,b1 for n-tile 2*p+1)
__device__ __forceinline__ void ldsm_x4_trans(uint32_t b[4], uint32_t addr) {
    asm volatile("ldmatrix.sync.aligned.m8n8.x4.trans.shared.b16 {%0,%1,%2,%3}, [%4];"
                 : "=r"(b[0]), "=r"(b[1]), "=r"(b[2]), "=r"(b[3]) : "r"(addr));
}

__device__ __forceinline__ void mma16816(float c[4], const uint32_t a[4],
                                         uint32_t b0, uint32_t b1) {
    asm volatile("mma.sync.aligned.m16n8k16.row.col.f32.bf16.bf16.f32 "
                 "{%0,%1,%2,%3}, {%4,%5,%6,%7}, {%8,%9}, {%0,%1,%2,%3};"
                 : "+f"(c[0]), "+f"(c[1]), "+f"(c[2]), "+f"(c[3])
                 : "r"(a[0]), "r"(a[1]), "r"(a[2]), "r"(a[3]), "r"(b0), "r"(b1));
}

__device__ __forceinline__ uint32_t pack_relu(float a, float b) {
    __nv_bfloat162 v = __float22bfloat162_rn(make_float2(fmaxf(a, 0.f), fmaxf(b, 0.f)));
    return *reinterpret_cast<uint32_t*>(&v);
}

__device__ __forceinline__ uint32_t pack_bf2(float a, float b) {
    __nv_bfloat162 v = __float22bfloat162_rn(make_float2(a, b));
    return *reinterpret_cast<uint32_t*>(&v);
}

__global__ __launch_bounds__(512, 1)
void flow_kernel(const float* __restrict__ x,  const float* __restrict__ W1,
                 const float* __restrict__ W2, const float* __restrict__ W3,
                 const float* __restrict__ M1, const float* __restrict__ M2,
                 const float* __restrict__ M3, const int* __restrict__ region_idx,
                 float* __restrict__ out)
{
    extern __shared__ unsigned char smem[];
    __nv_bfloat16* w1s = (__nv_bfloat16*)(smem + OFF_W1);
    __nv_bfloat16* w2s = (__nv_bfloat16*)(smem + OFF_W2);
    __nv_bfloat16* w3s = (__nv_bfloat16*)(smem + OFF_W3);
    float*         xsf = (float*)        (smem + OFF_XF);
    int*          ridx = (int*)          (smem + OFF_RIDX);

    const int tid  = threadIdx.x;
    const int w    = tid >> 5;          // warp 0..15
    const int lane = tid & 31;

    const int g    = lane >> 2;
    const int q    = lane & 3;
    const int l16  = lane & 15;
    const int lhi  = lane >> 4;
    const int mrow = w * 16;            // warp-private 16-row band within tile

    const uint32_t sbase = (uint32_t)__cvta_generic_to_shared(smem);
    const uint32_t b_w1_addr = sbase + OFF_W1 + (l16 * WS1 + lhi * 8) * 2;
    const uint32_t b_w2_addr = sbase + OFF_W2 + (l16 * WS2 + lhi * 8) * 2;
    const uint32_t b_w3_addr = sbase + OFF_W3 + (l16 * WS3 + lhi * 8) * 2;

    const float* xr0 = xsf + (mrow + g)     * XSF;   // epilogue / A-frag row ptrs
    const float* xr1 = xsf + (mrow + g + 8) * XSF;

    // ---- Persistent balanced schedule over 1024 (network, tile) units ----
    int       u  = (TOTAL_UNITS * blockIdx.x)       / NCTAS;
    const int u1 = (TOTAL_UNITS * (blockIdx.x + 1)) / NCTAS;

    while (u < u1) {
        const int net = u >> 3;         // network id r*B + b
        const int r   = net >> 4;       // B = 16

        // ---- Pre-mask this network's weights into bf16 SMEM, hidden dim
        //      relabeled by degree-sort (exact: relu is elementwise) ----
        __syncthreads();                // all warps done with previous weights
        if (tid < DD) ridx[tid] = region_idx[r * DD + tid];
        {
            const float* W1p = W1 + (size_t)net * DD * HH;
            const float* M1p = M1 + (size_t)net * DD * HH;
            for (int i = tid; i < DD * HH; i += 512) {
                int d = i >> 7, h = i & 127;
                w1s[d * WS1 + hpos(h)] = __float2bfloat16(W1p[i] * M1p[i]);
            }
            const float* W2p = W2 + (size_t)net * HH * HH;
            const float* M2p = M2 + (size_t)net * HH * HH;
            for (int i = tid; i < HH * HH; i += 512) {
                int k = i >> 7, j = i & 127;
                w2s[hpos(k) * WS2 + hpos(j)] = __float2bfloat16(W2p[i] * M2p[i]);
            }
            const float* W3p = W3 + (size_t)net * HH * 2 * DD;
            const float* M3p = M3 + (size_t)net * HH * 2 * DD;
            for (int i = tid; i < HH * 2 * DD; i += 512) {
                int k = i >> 6, o = i & 63;
                w3s[hpos(k) * WS3 + o] = __float2bfloat16(W3p[i] * M3p[i]);
            }
        }
        __syncthreads();
        const int col = ridx[lane];     // lane <-> feature column for this region

        const int uend = min(u1, (net + 1) * TILES_PER_NET);
        for (; u < uend; ++u) {
            const int t0 = (u & 7) * TILE;

            // ---- Load x tile (warp-private rows, lane = feature col) ----
            #pragma unroll 4
            for (int rr = 0; rr < 16; ++rr) {
                int row = mrow + rr;
                xsf[row * XSF + lane] = x[(size_t)(t0 + row) * FF + col];
            }
            __syncwarp();

            // ---- Build GEMM1 A-fragments straight from fp32 x ----
            uint32_t a1[2][4];
            #pragma unroll
            for (int k = 0; k < 2; ++k) {
                float2 p0 = *(const float2*)(xr0 + 16 * k + 2 * q);
                float2 p1 = *(const float2*)(xr1 + 16 * k + 2 * q);
                float2 p2 = *(const float2*)(xr0 + 16 * k + 2 * q + 8);
                float2 p3 = *(const float2*)(xr1 + 16 * k + 2 * q + 8);
                a1[k][0] = pack_bf2(p0.x, p0.y);
                a1[k][1] = pack_bf2(p1.x, p1.y);
                a1[k][2] = pack_bf2(p2.x, p2.y);
                a1[k][3] = pack_bf2(p3.x, p3.y);
            }

            // ---- GEMM1: h1 = relu(x[16,32] @ W1[32,128]) -> registers (a2) ----
            // (h1 columns are in degree-sorted order)
            uint32_t a2[8][4];
            #pragma unroll
            for (int p = 0; p < 4; ++p) {       // n-tile pairs for ILP
                float cA[2][4] = {{0.f,0.f,0.f,0.f},{0.f,0.f,0.f,0.f}};
                float cB[2][4] = {{0.f,0.f,0.f,0.f},{0.f,0.f,0.f,0.f}};
                #pragma unroll
                for (int k = 0; k < 2; ++k) {
                    uint32_t bA[4], bB[4];
                    ldsm_x4_trans(bA, b_w1_addr + (k * 16 * WS1 + (2*p)   * 16) * 2);
                    ldsm_x4_trans(bB, b_w1_addr + (k * 16 * WS1 + (2*p+1) * 16) * 2);
                    mma16816(cA[0], a1[k], bA[0], bA[1]);
                    mma16816(cA[1], a1[k], bA[2], bA[3]);
                    mma16816(cB[0], a1[k], bB[0], bB[1]);
                    mma16816(cB[1], a1[k], bB[2], bB[3]);
                }
                a2[2*p][0]   = pack_relu(cA[0][0], cA[0][1]);
                a2[2*p][1]   = pack_relu(cA[0][2], cA[0][3]);
                a2[2*p][2]   = pack_relu(cA[1][0], cA[1][1]);
                a2[2*p][3]   = pack_relu(cA[1][2], cA[1][3]);
                a2[2*p+1][0] = pack_relu(cB[0][0], cB[0][1]);
                a2[2*p+1][1] = pack_relu(cB[0][2], cB[0][3]);
                a2[2*p+1][2] = pack_relu(cB[1][0], cB[1][1]);
                a2[2*p+1][3] = pack_relu(cB[1][2], cB[1][3]);
            }

            // ---- GEMM2: h2 = relu(h1 @ W2) -> registers (a3) ----
            // Degree-sorted W2 is block-upper-triangular: pair p needs only
            // k-blocks 0..2p+1 (the rest are exactly zero -> skipped, exact).
            uint32_t a3[8][4];
            #pragma unroll
            for (int p = 0; p < 4; ++p) {
                float cA[2][4] = {{0.f,0.f,0.f,0.f},{0.f,0.f,0.f,0.f}};
                float cB[2][4] = {{0.f,0.f,0.f,0.f},{0.f,0.f,0.f,0.f}};
                #pragma unroll
                for (int k = 0; k < 2 * p + 2; ++k) {
                    uint32_t bA[4], bB[4];
                    ldsm_x4_trans(bA, b_w2_addr + (k * 16 * WS2 + (2*p)   * 16) * 2);
                    ldsm_x4_trans(bB, b_w2_addr + (k * 16 * WS2 + (2*p+1) * 16) * 2);
                    mma16816(cA[0], a2[k], bA[0], bA[1]);
                    mma16816(cA[1], a2[k], bA[2], bA[3]);
                    mma16816(cB[0], a2[k], bB[0], bB[1]);
                    mma16816(cB[1], a2[k], bB[2], bB[3]);
                }
                a3[2*p][0]   = pack_relu(cA[0][0], cA[0][1]);
                a3[2*p][1]   = pack_relu(cA[0][2], cA[0][3]);
                a3[2*p][2]   = pack_relu(cA[1][0], cA[1][1]);
                a3[2*p][3]   = pack_relu(cA[1][2], cA[1][3]);
                a3[2*p+1][0] = pack_relu(cB[0][0], cB[0][1]);
                a3[2*p+1][1] = pack_relu(cB[0][2], cB[0][3]);
                a3[2*p+1][2] = pack_relu(cB[1][0], cB[1][1]);
                a3[2*p+1][3] = pack_relu(cB[1][2], cB[1][3]);
            }

            // ---- GEMM3 + MAF epilogue (h2 in registers, degree-sorted k) ----
            float acc0 = 0.f, acc1 = 0.f;
            #pragma unroll
            for (int p = 0; p < 2; ++p) {
                float cA[2][4] = {{0.f,0.f,0.f,0.f},{0.f,0.f,0.f,0.f}};
                float cB[2][4] = {{0.f,0.f,0.f,0.f},{0.f,0.f,0.f,0.f}};
                #pragma unroll
                for (int k = 0; k < 8; ++k) {
                    uint32_t bA[4], bB[4];
                    ldsm_x4_trans(bA, b_w3_addr + (k * 16 * WS3 + (2*p)   * 16) * 2);
                    ldsm_x4_trans(bB, b_w3_addr + (k * 16 * WS3 + (2*p+1) * 16) * 2);
                    mma16816(cA[0], a3[k], bA[0], bA[1]);
                    mma16816(cA[1], a3[k], bA[2], bA[3]);
                    mma16816(cB[0], a3[k], bB[0], bB[1]);
                    mma16816(cB[1], a3[k], bB[2], bB[3]);
                }
                // cols (2d, 2d+1) = (shift, log_scale) in the same thread:
                // nt2: even sub-tile d = 8*nt2 + q, odd sub-tile d = 8*nt2 + 4 + q
                #pragma unroll
                for (int s = 0; s < 2; ++s) {
                    const float (*cc)[4] = s ? cB : cA;
                    int de = 8 * (2*p + s) + q, dd = de + 4;
                    float u0 = (xr0[de] - cc[0][0]) * __expf(-cc[0][1]);
                    float u1v = (xr1[de] - cc[0][2]) * __expf(-cc[0][3]);
                    float u2 = (xr0[dd] - cc[1][0]) * __expf(-cc[1][1]);
                    float u3 = (xr1[dd] - cc[1][2]) * __expf(-cc[1][3]);
                    acc0 += -0.5f * u0  * u0  - HALF_LOG_2PI - cc[0][1];
                    acc1 += -0.5f * u1v * u1v - HALF_LOG_2PI - cc[0][3];
                    acc0 += -0.5f * u2  * u2  - HALF_LOG_2PI - cc[1][1];
                    acc1 += -0.5f * u3  * u3  - HALF_LOG_2PI - cc[1][3];
                }
            }
            // quad reduction over the 4 lanes sharing a row (covers all 32 d)
            acc0 += __shfl_xor_sync(0xffffffffu, acc0, 1);
            acc0 += __shfl_xor_sync(0xffffffffu, acc0, 2);
            acc1 += __shfl_xor_sync(0xffffffffu, acc1, 1);
            acc1 += __shfl_xor_sync(0xffffffffu, acc1, 2);
            if (q == 0) {
                out[(size_t)(t0 + mrow + g)     * (RR * BB) + net] = acc0;
                out[(size_t)(t0 + mrow + g + 8) * (RR * BB) + net] = acc1;
            }
            __syncwarp();   // protect x tile before next iteration overwrites
        }
    }
}

extern "C" void kernel_launch(void* const* d_in, const int* in_sizes, int n_in,
                              void* d_out, int out_size)
{
    const float* x   = (const float*)d_in[0];
    const float* W1  = (const float*)d_in[1];
    const float* W2  = (const float*)d_in[2];
    const float* W3  = (const float*)d_in[3];
    const float* M1  = (const float*)d_in[4];
    const float* M2  = (const float*)d_in[5];
    const float* M3  = (const float*)d_in[6];
    const int*  ridx = (const int*)  d_in[7];
    float* out = (float*)d_out;

    cudaFuncSetAttribute(flow_kernel, cudaFuncAttributeMaxDynamicSharedMemorySize,
                         SMEM_TOTAL);
    flow_kernel<<<NCTAS, 512, SMEM_TOTAL>>>(x, W1, W2, W3, M1, M2, M3, ridx, out);
}